// round 4
// baseline (speedup 1.0000x reference)
#include <cuda_runtime.h>
#include <math.h>

#define BDIM 512
#define TDIM 512
#define IN0  64
#define HDIM 128
#define G3   384   // 3*H  (gate order r, z, n)

typedef unsigned long long u64;

// ---------------------------------------------------------------------------
// f32x2 packed helpers
// ---------------------------------------------------------------------------
__device__ __forceinline__ u64 splat2(unsigned int v) {
    u64 r; asm("mov.b64 %0, {%1, %1};" : "=l"(r) : "r"(v)); return r;
}
__device__ __forceinline__ void fma2(u64& d, u64 a, u64 b) {
    asm("fma.rn.f32x2 %0, %1, %2, %0;" : "+l"(d) : "l"(a), "l"(b));
}
__device__ __forceinline__ u64 add2(u64 a, u64 b) {
    u64 r; asm("add.rn.f32x2 %0, %1, %2;" : "=l"(r) : "l"(a), "l"(b)); return r;
}
__device__ __forceinline__ float2 unpack2(u64 v) {
    unsigned int lo, hi;
    asm("mov.b64 {%0, %1}, %2;" : "=r"(lo), "=r"(hi) : "l"(v));
    float2 f; f.x = __uint_as_float(lo); f.y = __uint_as_float(hi); return f;
}

// ---------------------------------------------------------------------------
// Scratch
// ---------------------------------------------------------------------------
__device__ float g_gi   [(size_t)BDIM * TDIM * G3];
__device__ float g_h1   [(size_t)BDIM * TDIM * HDIM];
__device__ float g_hlast[(size_t)BDIM * HDIM];

// ---------------------------------------------------------------------------
// gi GEMM (round-2 proven): out[M,384] = X[M,K] @ W[384,K]^T + bias
// ---------------------------------------------------------------------------
template <int K>
__global__ __launch_bounds__(256)
void gi_gemm(const float* __restrict__ X,
             const float* __restrict__ W,
             const float* __restrict__ bias)
{
    constexpr int TM  = 64;
    constexpr int NC  = 96;
    constexpr int XP  = 66;
    constexpr int WP2 = 98;

    extern __shared__ float sm[];
    float* xs = sm;
    float* ws = sm + K * XP;

    const int tid = threadIdx.x;
    const int rowbase = blockIdx.x * TM;

    for (int idx = tid; idx < TM * K; idx += 256) {
        int r = idx / K, k = idx - r * K;
        xs[k * XP + r] = X[(size_t)(rowbase + r) * K + k];
    }

    const int rg = tid >> 4;
    const int gg = tid & 15;
    float* out = g_gi;

    for (int c = 0; c < 4; ++c) {
        __syncthreads();
        for (int idx = tid; idx < NC * K; idx += 256) {
            int g = idx / K, k = idx - g * K;
            ws[k * WP2 + g] = W[(size_t)(c * NC + g) * K + k];
        }
        __syncthreads();

        u64 acc[4][3];
        #pragma unroll
        for (int i = 0; i < 4; ++i)
            #pragma unroll
            for (int p = 0; p < 3; ++p) acc[i][p] = 0ull;

        const float* xp0 = &xs[rg * 4];
        const float* wp0 = &ws[gg * 6];

        #pragma unroll 4
        for (int k = 0; k < K; ++k) {
            u64 x0 = splat2(__float_as_uint(xp0[k * XP + 0]));
            u64 x1 = splat2(__float_as_uint(xp0[k * XP + 1]));
            u64 x2 = splat2(__float_as_uint(xp0[k * XP + 2]));
            u64 x3 = splat2(__float_as_uint(xp0[k * XP + 3]));
            const u64* wrow = (const u64*)&wp0[k * WP2];
            u64 w01 = wrow[0], w23 = wrow[1], w45 = wrow[2];
            fma2(acc[0][0], x0, w01); fma2(acc[0][1], x0, w23); fma2(acc[0][2], x0, w45);
            fma2(acc[1][0], x1, w01); fma2(acc[1][1], x1, w23); fma2(acc[1][2], x1, w45);
            fma2(acc[2][0], x2, w01); fma2(acc[2][1], x2, w23); fma2(acc[2][2], x2, w45);
            fma2(acc[3][0], x3, w01); fma2(acc[3][1], x3, w23); fma2(acc[3][2], x3, w45);
        }

        const int g0 = c * NC + gg * 6;
        #pragma unroll
        for (int p = 0; p < 3; ++p) {
            float b0 = bias[g0 + 2 * p];
            float b1 = bias[g0 + 2 * p + 1];
            #pragma unroll
            for (int i = 0; i < 4; ++i) {
                float2 v = unpack2(acc[i][p]);
                size_t r = (size_t)(rowbase + rg * 4 + i);
                out[r * G3 + g0 + 2 * p]     = v.x + b0;
                out[r * G3 + g0 + 2 * p + 1] = v.y + b1;
            }
        }
    }
}

// ---------------------------------------------------------------------------
// Persistent GRU recurrence, v4: 1024 threads/CTA (8 warps/SMSP for latency
// hiding). q = tid&7 (k-eighth, intra-warp), j = tid>>3 (hidden unit).
// r weights in regs (16); z/n weights in smem ordered by consuming tid
// (coalesced LDS.32). h double-buffered in smem -> ONE barrier/step.
// Reduction over q: 3 shfl rounds (xor4 packed, then xor2/xor1 on q&3).
// Sequence output written coalesced (b=tid>>7, j=tid&127) after the barrier.
// ---------------------------------------------------------------------------
template <int WRITE_SEQ>
__global__ __launch_bounds__(1024, 1)
void gru_recurrent(const float* __restrict__ Whh,
                   const float* __restrict__ bhh)
{
    extern __shared__ float sm[];
    float* Wz_s = sm;                  // [16][1024]  Wz_s[kk*1024 + tid]
    float* Wn_s = sm + 16 * 1024;      // [16][1024]
    float* hs   = Wn_s + 16 * 1024;    // [2][128][4] double-buffered h

    const int tid = threadIdx.x;
    const int q   = tid & 7;
    const int j   = tid >> 3;
    const int qq  = q & 3;
    const int b0  = blockIdx.x * 4;

    // Stage z/n weights ordered by consuming thread (one-time).
    for (int idx = tid; idx < 16 * 1024; idx += 1024) {
        int kk = idx >> 10;
        int t2 = idx & 1023;
        int j2 = t2 >> 3, q2 = t2 & 7;
        int k  = 8 * kk + q2;
        Wz_s[idx] = Whh[(size_t)(HDIM + j2) * HDIM + k];
        Wn_s[idx] = Whh[(size_t)(2 * HDIM + j2) * HDIM + k];
    }
    for (int idx = tid; idx < 2 * 512; idx += 1024) hs[idx] = 0.f;

    // r-gate weights into registers (k = 8*kk + q).
    unsigned int wr[16];
    #pragma unroll
    for (int kk = 0; kk < 16; ++kk)
        wr[kk] = __float_as_uint(__ldg(Whh + (size_t)j * HDIM + 8 * kk + q));

    const float bhr = bhh[j];
    const float bhz = bhh[HDIM + j];
    const float bhn = bhh[2 * HDIM + j];

    __syncthreads();

    const float* gi = g_gi + (size_t)(b0 + qq) * TDIM * G3;
    const bool hi  = qq >= 2;
    const bool odd = qq & 1;
    float hprev = 0.f;

    for (int t = 0; t < TDIM; ++t) {
        // Prefetch input-side preactivations (hidden behind the matvec).
        const float* gip = gi + (size_t)t * G3;
        float ir  = gip[j];
        float iz  = gip[HDIM + j];
        float in_ = gip[2 * HDIM + j];

        const u64*   h2  = (const u64*)(hs + (t & 1) * 512);
        const float* wzp = Wz_s + tid;
        const float* wnp = Wn_s + tid;

        u64 a_r01 = 0, a_r23 = 0, a_z01 = 0, a_z23 = 0, a_n01 = 0, a_n23 = 0;

        #pragma unroll
        for (int kk = 0; kk < 16; ++kk) {
            int k = 8 * kk + q;
            u64 h01 = h2[k * 2];       // 8 distinct addrs/warp -> distinct banks
            u64 h23 = h2[k * 2 + 1];
            u64 wr2 = splat2(wr[kk]);
            u64 wz2 = splat2(__float_as_uint(wzp[kk * 1024]));
            u64 wn2 = splat2(__float_as_uint(wnp[kk * 1024]));
            fma2(a_r01, wr2, h01); fma2(a_r23, wr2, h23);
            fma2(a_z01, wz2, h01); fma2(a_z23, wz2, h23);
            fma2(a_n01, wn2, h01); fma2(a_n23, wn2, h23);
        }

        // Round 1 (xor 4): fold k-groups q and q+4 (packed adds).
        a_r01 = add2(a_r01, __shfl_xor_sync(0xFFFFFFFFu, a_r01, 4));
        a_r23 = add2(a_r23, __shfl_xor_sync(0xFFFFFFFFu, a_r23, 4));
        a_z01 = add2(a_z01, __shfl_xor_sync(0xFFFFFFFFu, a_z01, 4));
        a_z23 = add2(a_z23, __shfl_xor_sync(0xFFFFFFFFu, a_z23, 4));
        a_n01 = add2(a_n01, __shfl_xor_sync(0xFFFFFFFFu, a_n01, 4));
        a_n23 = add2(a_n23, __shfl_xor_sync(0xFFFFFFFFu, a_n23, 4));

        float2 r01 = unpack2(a_r01), r23 = unpack2(a_r23);
        float2 z01 = unpack2(a_z01), z23 = unpack2(a_z23);
        float2 n01 = unpack2(a_n01), n23 = unpack2(a_n23);

        // Round 2 (xor 2): keep own batch-pair, add the other k-half.
        float ra = hi ? r23.x : r01.x,  rb = hi ? r23.y : r01.y;
        float za = hi ? z23.x : z01.x,  zb = hi ? z23.y : z01.y;
        float na = hi ? n23.x : n01.x,  nb = hi ? n23.y : n01.y;
        ra += __shfl_xor_sync(0xFFFFFFFFu, hi ? r01.x : r23.x, 2);
        rb += __shfl_xor_sync(0xFFFFFFFFu, hi ? r01.y : r23.y, 2);
        za += __shfl_xor_sync(0xFFFFFFFFu, hi ? z01.x : z23.x, 2);
        zb += __shfl_xor_sync(0xFFFFFFFFu, hi ? z01.y : z23.y, 2);
        na += __shfl_xor_sync(0xFFFFFFFFu, hi ? n01.x : n23.x, 2);
        nb += __shfl_xor_sync(0xFFFFFFFFu, hi ? n01.y : n23.y, 2);
        // Round 3 (xor 1): keep own parity batch.
        float sr = (odd ? rb : ra) + __shfl_xor_sync(0xFFFFFFFFu, odd ? ra : rb, 1);
        float sz = (odd ? zb : za) + __shfl_xor_sync(0xFFFFFFFFu, odd ? za : zb, 1);
        float sn = (odd ? nb : na) + __shfl_xor_sync(0xFFFFFFFFu, odd ? na : nb, 1);

        // Gate phase: lane q (=qq, q<4) owns (hidden j, batch qq).
        if (q < 4) {
            float r = __fdividef(1.f, 1.f + __expf(-(ir + sr + bhr)));
            float z = __fdividef(1.f, 1.f + __expf(-(iz + sz + bhz)));
            float n = tanhf(in_ + r * (sn + bhn));
            float hnew = n + z * (hprev - n);
            hprev = hnew;
            hs[((t + 1) & 1) * 512 + j * 4 + qq] = hnew;
        }
        __syncthreads();   // single barrier per step

        // Coalesced sequence write from the freshly-synced buffer.
        if (WRITE_SEQ) {
            if (tid < 512) {
                int b  = tid >> 7;
                int jj = tid & 127;
                float hv = hs[((t + 1) & 1) * 512 + jj * 4 + b];
                g_h1[((size_t)(b0 + b) * TDIM + t) * HDIM + jj] = hv;
            }
        } else if (t == TDIM - 1) {
            if (tid < 512) {
                int b  = tid >> 7;
                int jj = tid & 127;
                g_hlast[(size_t)(b0 + b) * HDIM + jj] =
                    hs[((t + 1) & 1) * 512 + jj * 4 + b];
            }
        }
    }
}

// ---------------------------------------------------------------------------
// Final FC (O = 1): one warp per batch.
// ---------------------------------------------------------------------------
__global__ void fc_kernel(const float* __restrict__ Wfc,
                          const float* __restrict__ bfc,
                          float* __restrict__ out)
{
    int w = (blockIdx.x * blockDim.x + threadIdx.x) >> 5;
    int lane = threadIdx.x & 31;
    if (w >= BDIM) return;
    const float* hp = g_hlast + (size_t)w * HDIM;
    float s = 0.f;
    #pragma unroll
    for (int k = lane; k < HDIM; k += 32) s += hp[k] * Wfc[k];
    #pragma unroll
    for (int o = 16; o; o >>= 1) s += __shfl_xor_sync(0xFFFFFFFFu, s, o);
    if (lane == 0) out[w] = s + bfc[0];
}

// ---------------------------------------------------------------------------
extern "C" void kernel_launch(void* const* d_in, const int* in_sizes, int n_in,
                              void* d_out, int out_size)
{
    const float* x     = (const float*)d_in[0];
    const float* W_ih0 = (const float*)d_in[1];
    const float* W_hh0 = (const float*)d_in[2];
    const float* b_ih0 = (const float*)d_in[3];
    const float* b_hh0 = (const float*)d_in[4];
    const float* W_ih1 = (const float*)d_in[5];
    const float* W_hh1 = (const float*)d_in[6];
    const float* b_ih1 = (const float*)d_in[7];
    const float* b_hh1 = (const float*)d_in[8];
    const float* W_fc  = (const float*)d_in[9];
    const float* b_fc  = (const float*)d_in[10];
    float* out = (float*)d_out;

    const int SMEM_G64  = (64  * 66 + 64  * 98) * 4;
    const int SMEM_G128 = (128 * 66 + 128 * 98) * 4;
    const int SMEM_REC  = (2 * 16 * 1024 + 2 * 512) * 4;   // 135,168 B

    cudaFuncSetAttribute(gi_gemm<64>,  cudaFuncAttributeMaxDynamicSharedMemorySize, SMEM_G64);
    cudaFuncSetAttribute(gi_gemm<128>, cudaFuncAttributeMaxDynamicSharedMemorySize, SMEM_G128);
    cudaFuncSetAttribute(gru_recurrent<1>, cudaFuncAttributeMaxDynamicSharedMemorySize, SMEM_REC);
    cudaFuncSetAttribute(gru_recurrent<0>, cudaFuncAttributeMaxDynamicSharedMemorySize, SMEM_REC);

    void* h1ptr = nullptr;
    cudaGetSymbolAddress(&h1ptr, g_h1);

    const int M = BDIM * TDIM;
    const int GEMM_GRID = M / 64;

    gi_gemm<64><<<GEMM_GRID, 256, SMEM_G64>>>(x, W_ih0, b_ih0);
    gru_recurrent<1><<<BDIM / 4, 1024, SMEM_REC>>>(W_hh0, b_hh0);
    gi_gemm<128><<<GEMM_GRID, 256, SMEM_G128>>>((const float*)h1ptr, W_ih1, b_ih1);
    gru_recurrent<0><<<BDIM / 4, 1024, SMEM_REC>>>(W_hh1, b_hh1);
    fc_kernel<<<BDIM / 4, 128>>>(W_fc, b_fc, out);
}

// round 5
// speedup vs baseline: 1.6592x; 1.6592x over previous
#include <cuda_runtime.h>
#include <math.h>

#define BDIM 512
#define TDIM 512
#define IN0  64
#define HDIM 128
#define G3   384   // 3*H  (gate order r, z, n)

typedef unsigned long long u64;

// ---------------------------------------------------------------------------
// f32x2 packed helpers
// ---------------------------------------------------------------------------
__device__ __forceinline__ u64 splat2(unsigned int v) {
    u64 r; asm("mov.b64 %0, {%1, %1};" : "=l"(r) : "r"(v)); return r;
}
__device__ __forceinline__ void fma2(u64& d, u64 a, u64 b) {
    asm("fma.rn.f32x2 %0, %1, %2, %0;" : "+l"(d) : "l"(a), "l"(b));
}
__device__ __forceinline__ float2 unpack2(u64 v) {
    unsigned int lo, hi;
    asm("mov.b64 {%0, %1}, %2;" : "=r"(lo), "=r"(hi) : "l"(v));
    float2 f; f.x = __uint_as_float(lo); f.y = __uint_as_float(hi); return f;
}

// ---------------------------------------------------------------------------
// Scratch
// ---------------------------------------------------------------------------
__device__ float g_gi   [(size_t)BDIM * TDIM * G3];
__device__ float g_h1   [(size_t)BDIM * TDIM * HDIM];
__device__ float g_hlast[(size_t)BDIM * HDIM];

// ---------------------------------------------------------------------------
// gi GEMM: out[M,384] = X[M,K] @ W[384,K]^T + bias.  CTA = 64 rows, 256 thr.
// v5: output staged in smem, flushed with coalesced STG.128.
// ---------------------------------------------------------------------------
template <int K>
__global__ __launch_bounds__(256)
void gi_gemm(const float* __restrict__ X,
             const float* __restrict__ W,
             const float* __restrict__ bias)
{
    constexpr int TM  = 64;
    constexpr int NC  = 96;
    constexpr int XP  = 66;
    constexpr int WP2 = 98;

    extern __shared__ float sm[];
    float* xs = sm;              // [K][XP]
    float* ws = sm + K * XP;     // [K][WP2] weights; reused as [64][96] staging

    const int tid = threadIdx.x;
    const int rowbase = blockIdx.x * TM;

    for (int idx = tid; idx < TM * K; idx += 256) {
        int r = idx / K, k = idx - r * K;
        xs[k * XP + r] = X[(size_t)(rowbase + r) * K + k];
    }

    const int rg = tid >> 4;
    const int gg = tid & 15;
    float* out = g_gi;

    for (int c = 0; c < 4; ++c) {
        __syncthreads();
        for (int idx = tid; idx < NC * K; idx += 256) {
            int g = idx / K, k = idx - g * K;
            ws[k * WP2 + g] = W[(size_t)(c * NC + g) * K + k];
        }
        __syncthreads();

        u64 acc[4][3];
        #pragma unroll
        for (int i = 0; i < 4; ++i)
            #pragma unroll
            for (int p = 0; p < 3; ++p) acc[i][p] = 0ull;

        const float* xp0 = &xs[rg * 4];
        const float* wp0 = &ws[gg * 6];

        #pragma unroll 4
        for (int k = 0; k < K; ++k) {
            u64 x0 = splat2(__float_as_uint(xp0[k * XP + 0]));
            u64 x1 = splat2(__float_as_uint(xp0[k * XP + 1]));
            u64 x2 = splat2(__float_as_uint(xp0[k * XP + 2]));
            u64 x3 = splat2(__float_as_uint(xp0[k * XP + 3]));
            const u64* wrow = (const u64*)&wp0[k * WP2];
            u64 w01 = wrow[0], w23 = wrow[1], w45 = wrow[2];
            fma2(acc[0][0], x0, w01); fma2(acc[0][1], x0, w23); fma2(acc[0][2], x0, w45);
            fma2(acc[1][0], x1, w01); fma2(acc[1][1], x1, w23); fma2(acc[1][2], x1, w45);
            fma2(acc[2][0], x2, w01); fma2(acc[2][1], x2, w23); fma2(acc[2][2], x2, w45);
            fma2(acc[3][0], x3, w01); fma2(acc[3][1], x3, w23); fma2(acc[3][2], x3, w45);
        }

        __syncthreads();  // done reading weights; reuse ws as staging

        const int g0 = c * NC + gg * 6;
        #pragma unroll
        for (int p = 0; p < 3; ++p) {
            float b0 = bias[g0 + 2 * p];
            float b1 = bias[g0 + 2 * p + 1];
            #pragma unroll
            for (int i = 0; i < 4; ++i) {
                float2 v = unpack2(acc[i][p]);
                int r = rg * 4 + i;
                ws[r * NC + gg * 6 + 2 * p]     = v.x + b0;
                ws[r * NC + gg * 6 + 2 * p + 1] = v.y + b1;
            }
        }
        __syncthreads();

        // Coalesced flush: 64 rows x 96 gates, float4 granularity.
        #pragma unroll
        for (int v = 0; v < (TM * NC / 4) / 256; ++v) {
            int idx = (v * 256 + tid) * 4;
            int r = idx / NC, col = idx - r * NC;
            float4 val = *(const float4*)&ws[idx];
            *(float4*)&out[(size_t)(rowbase + r) * G3 + c * NC + col] = val;
        }
    }
}

// ---------------------------------------------------------------------------
// Persistent GRU recurrence, v5 (v2 shape + LDS diet).
// 512 thr: j = tid&127 (hidden unit), q = tid>>7 (k-quarter, inter-warp).
// r/z weights in regs; n weights quad-loaded (LDS.128 per 4 k) from
// consuming-tid-ordered smem; h loaded as one LDS.128 broadcast per k.
// Reduction via smem (RP=13), 2 barriers/step (proven layout).
// ---------------------------------------------------------------------------
template <int WRITE_SEQ>
__global__ __launch_bounds__(512, 1)
void gru_recurrent(const float* __restrict__ Whh,
                   const float* __restrict__ bhh)
{
    constexpr int RP = 13;

    extern __shared__ float sm[];
    float* Wn4 = sm;                     // [8][512][4]: quad m = kk&3, kkg = kk>>2
    float* hs  = Wn4 + 8 * 512 * 4;      // [128][4], 16B-aligned (offset 64KB)
    float* red = hs + HDIM * 4;          // [4][128][RP]
    float* bh  = red + 4 * HDIM * RP;    // [384]

    const int tid = threadIdx.x;
    const int j   = tid & 127;
    const int q   = tid >> 7;
    const int b0  = blockIdx.x * 4;
    const int k0  = q * 32;

    // Stage n-gate weights: slot (kkg, t2, m) = Wn[j2][k2] with
    // j2 = t2&127, q2 = t2>>7, k2 = q2*32 + kkg*4 + m.  (one-time)
    for (int idx = tid; idx < 8 * 512 * 4; idx += 512) {
        int kkg = idx >> 11;
        int rem = idx & 2047;
        int t2  = rem >> 2;
        int m   = rem & 3;
        int j2  = t2 & 127, q2 = t2 >> 7;
        int k2  = q2 * 32 + kkg * 4 + m;
        Wn4[idx] = Whh[(size_t)(2 * HDIM + j2) * HDIM + k2];
    }
    for (int idx = tid; idx < G3; idx += 512) bh[idx] = bhh[idx];
    for (int idx = tid; idx < HDIM * 4; idx += 512) hs[idx] = 0.f;

    // r/z weights into registers (k = k0 + kk).
    unsigned int wrz[64];
    #pragma unroll
    for (int kk = 0; kk < 32; ++kk) {
        wrz[2 * kk]     = __float_as_uint(__ldg(Whh + (size_t)j * HDIM + k0 + kk));
        wrz[2 * kk + 1] = __float_as_uint(__ldg(Whh + (size_t)(HDIM + j) * HDIM + k0 + kk));
    }
    const float bhr = bhh[j];
    const float bhz = bhh[HDIM + j];
    const float bhn = bhh[2 * HDIM + j];

    __syncthreads();

    float* myred = &red[(q * HDIM + j) * RP];
    const float* gi = g_gi + (size_t)(b0 + q) * TDIM * G3;
    const ulonglong2* h16 = (const ulonglong2*)hs;     // one 16B load per k
    const uint4* wn4p = (const uint4*)Wn4 + tid;       // stride 512 uint4 per kkg

    for (int t = 0; t < TDIM; ++t) {
        // Prefetch input-side preactivations (covered by the matvec).
        const float* gip = gi + (size_t)t * G3;
        float ir  = gip[j];
        float iz  = gip[HDIM + j];
        float in_ = gip[2 * HDIM + j];

        u64 a_r01 = 0, a_r23 = 0, a_z01 = 0, a_z23 = 0, a_n01 = 0, a_n23 = 0;

        #pragma unroll
        for (int kkg = 0; kkg < 8; ++kkg) {
            uint4 wq = wn4p[kkg * 512];                 // wn for 4 k, coalesced
            #pragma unroll
            for (int m = 0; m < 4; ++m) {
                int kk = kkg * 4 + m;
                ulonglong2 hv = h16[k0 + kk];           // LDS.128 broadcast
                u64 wr2 = splat2(wrz[2 * kk]);
                u64 wz2 = splat2(wrz[2 * kk + 1]);
                unsigned int wnu = (m == 0) ? wq.x : (m == 1) ? wq.y
                                 : (m == 2) ? wq.z : wq.w;
                u64 wn2 = splat2(wnu);
                fma2(a_r01, wr2, hv.x); fma2(a_r23, wr2, hv.y);
                fma2(a_z01, wz2, hv.x); fma2(a_z23, wz2, hv.y);
                fma2(a_n01, wn2, hv.x); fma2(a_n23, wn2, hv.y);
            }
        }

        {
            float2 v;
            v = unpack2(a_r01); myred[0]  = v.x; myred[1]  = v.y;
            v = unpack2(a_r23); myred[2]  = v.x; myred[3]  = v.y;
            v = unpack2(a_z01); myred[4]  = v.x; myred[5]  = v.y;
            v = unpack2(a_z23); myred[6]  = v.x; myred[7]  = v.y;
            v = unpack2(a_n01); myred[8]  = v.x; myred[9]  = v.y;
            v = unpack2(a_n23); myred[10] = v.x; myred[11] = v.y;
        }
        __syncthreads();

        // Gate phase: thread (j, q) finishes batch b = q.
        const int b = q;
        float sr = 0.f, sz = 0.f, sn = 0.f;
        #pragma unroll
        for (int qq = 0; qq < 4; ++qq) {
            const float* rp = &red[(qq * HDIM + j) * RP];
            sr += rp[0 * 4 + b];
            sz += rp[1 * 4 + b];
            sn += rp[2 * 4 + b];
        }
        float ghr = sr + bhr;
        float ghz = sz + bhz;
        float ghn = sn + bhn;
        float r = __fdividef(1.f, 1.f + __expf(-(ir + ghr)));
        float z = __fdividef(1.f, 1.f + __expf(-(iz + ghz)));
        float n = tanhf(in_ + r * ghn);
        float hold = hs[j * 4 + b];
        float hnew = n + z * (hold - n);

        hs[j * 4 + b] = hnew;
        if (WRITE_SEQ) {
            g_h1[((size_t)(b0 + b) * TDIM + t) * HDIM + j] = hnew;  // coalesced
        } else if (t == TDIM - 1) {
            g_hlast[(size_t)(b0 + b) * HDIM + j] = hnew;
        }
        __syncthreads();
    }
}

// ---------------------------------------------------------------------------
// Final FC (O = 1): one warp per batch.
// ---------------------------------------------------------------------------
__global__ void fc_kernel(const float* __restrict__ Wfc,
                          const float* __restrict__ bfc,
                          float* __restrict__ out)
{
    int w = (blockIdx.x * blockDim.x + threadIdx.x) >> 5;
    int lane = threadIdx.x & 31;
    if (w >= BDIM) return;
    const float* hp = g_hlast + (size_t)w * HDIM;
    float s = 0.f;
    #pragma unroll
    for (int k = lane; k < HDIM; k += 32) s += hp[k] * Wfc[k];
    #pragma unroll
    for (int o = 16; o; o >>= 1) s += __shfl_xor_sync(0xFFFFFFFFu, s, o);
    if (lane == 0) out[w] = s + bfc[0];
}

// ---------------------------------------------------------------------------
extern "C" void kernel_launch(void* const* d_in, const int* in_sizes, int n_in,
                              void* d_out, int out_size)
{
    const float* x     = (const float*)d_in[0];
    const float* W_ih0 = (const float*)d_in[1];
    const float* W_hh0 = (const float*)d_in[2];
    const float* b_ih0 = (const float*)d_in[3];
    const float* b_hh0 = (const float*)d_in[4];
    const float* W_ih1 = (const float*)d_in[5];
    const float* W_hh1 = (const float*)d_in[6];
    const float* b_ih1 = (const float*)d_in[7];
    const float* b_hh1 = (const float*)d_in[8];
    const float* W_fc  = (const float*)d_in[9];
    const float* b_fc  = (const float*)d_in[10];
    float* out = (float*)d_out;

    const int SMEM_G64  = (64  * 66 + 64  * 98) * 4;
    const int SMEM_G128 = (128 * 66 + 128 * 98) * 4;
    const int SMEM_REC  = (8 * 512 * 4 + HDIM * 4 + 4 * HDIM * 13 + G3) * 4; // 95,744 B

    cudaFuncSetAttribute(gi_gemm<64>,  cudaFuncAttributeMaxDynamicSharedMemorySize, SMEM_G64);
    cudaFuncSetAttribute(gi_gemm<128>, cudaFuncAttributeMaxDynamicSharedMemorySize, SMEM_G128);
    cudaFuncSetAttribute(gru_recurrent<1>, cudaFuncAttributeMaxDynamicSharedMemorySize, SMEM_REC);
    cudaFuncSetAttribute(gru_recurrent<0>, cudaFuncAttributeMaxDynamicSharedMemorySize, SMEM_REC);

    void* h1ptr = nullptr;
    cudaGetSymbolAddress(&h1ptr, g_h1);

    const int M = BDIM * TDIM;
    const int GEMM_GRID = M / 64;

    gi_gemm<64><<<GEMM_GRID, 256, SMEM_G64>>>(x, W_ih0, b_ih0);
    gru_recurrent<1><<<BDIM / 4, 512, SMEM_REC>>>(W_hh0, b_hh0);
    gi_gemm<128><<<GEMM_GRID, 256, SMEM_G128>>>((const float*)h1ptr, W_ih1, b_ih1);
    gru_recurrent<0><<<BDIM / 4, 512, SMEM_REC>>>(W_hh1, b_hh1);
    fc_kernel<<<BDIM / 4, 128>>>(W_fc, b_fc, out);
}